// round 7
// baseline (speedup 1.0000x reference)
#include <cuda_runtime.h>

#define IN_H   1024
#define IN_W   1024
#define OUT_H  256
#define OUT_W  256
#define NTAP   16

#define VCHUNK 4                    // output rows per strip (register-lean)
#define VROWS  (4*VCHUNK + 12)      // 28 input rows feed 4 output rows
#define STRIPS_PER_BLOCK 2
#define NSTRIPS (OUT_H / VCHUNK)                      // 64
#define XBLKS   (NSTRIPS / STRIPS_PER_BLOCK)          // 32

// ---------------------------------------------------------------------------
// Fused separable bicubic 4x downsample, tuned for high co-residency:
// VCHUNK=4 -> 16 acc regs, 16 KB smem -> 6+ CTAs/SM, so other CTAs' V-phase
// LDG streams cover each CTA's H-phase dead time. Halo redundancy (1.75x)
// hits L2 only; DRAM traffic stays at the ~104 MB unique floor.
// ---------------------------------------------------------------------------
__global__ __launch_bounds__(256, 6)
void bicubic_fused(const float* __restrict__ in, float* __restrict__ out)
{
    constexpr float W[NTAP] = {
        -0.001708984375f, -0.010986328125f, -0.018310546875f, -0.011962890625f,
         0.022705078125f,  0.097412109375f,  0.181884765625f,  0.240966796875f,
         0.240966796875f,  0.181884765625f,  0.097412109375f,  0.022705078125f,
        -0.011962890625f, -0.018310546875f, -0.010986328125f, -0.001708984375f };

    __shared__ __align__(16) float s[VCHUNK][IN_W];   // 16 KB

    const int tid = threadIdx.x;                 // float4-column 0..255
    const int img = blockIdx.y;

    const float4* __restrict__ inp =
        (const float4*)(in + (size_t)img * (IN_H * IN_W));

#pragma unroll 1
    for (int it = 0; it < STRIPS_PER_BLOCK; ++it) {
        const int strip = blockIdx.x + XBLKS * it;   // 0..63
        const int o0    = strip * VCHUNK;
        const int R0    = 4 * o0 - 6;

        // ---- Phase V: vertical 16-tap into registers ----
        float4 acc[VCHUNK];
#pragma unroll
        for (int j = 0; j < VCHUNK; ++j) acc[j] = make_float4(0.f, 0.f, 0.f, 0.f);

#pragma unroll
        for (int i = 0; i < VROWS; ++i) {
            const int gr = min(max(R0 + i, 0), IN_H - 1);
            const float4 v = __ldg(inp + (size_t)gr * (IN_W / 4) + tid);
#pragma unroll
            for (int j = 0; j < VCHUNK; ++j) {
                const int k = i - 4 * j;         // tap index (compile-time pruned)
                if (k >= 0 && k < NTAP) {
                    acc[j].x = fmaf(W[k], v.x, acc[j].x);
                    acc[j].y = fmaf(W[k], v.y, acc[j].y);
                    acc[j].z = fmaf(W[k], v.z, acc[j].z);
                    acc[j].w = fmaf(W[k], v.w, acc[j].w);
                }
            }
        }

        // ---- dump strip to smem: STS.128, conflict-free ----
#pragma unroll
        for (int j = 0; j < VCHUNK; ++j)
            ((float4*)s[j])[tid] = acc[j];
        __syncthreads();

        // ---- Phase H: horizontal 16-tap, one output column per thread ----
        const int oc = tid;
        float* __restrict__ outp =
            out + ((size_t)img * OUT_H + o0) * OUT_W + oc;

#pragma unroll
        for (int j = 0; j < VCHUNK; ++j) {
            const float* __restrict__ srow = s[j];
            float r;
            if (oc >= 2 && oc <= 253) {
                const float4* __restrict__ sv = (const float4*)srow;
                const float4 a = sv[oc - 2];
                const float4 b = sv[oc - 1];
                const float4 c = sv[oc];
                const float4 d = sv[oc + 1];
                const float4 e = sv[oc + 2];
                r = W[0] * a.z;                  // tap 0 = s[4oc-6]
                r = fmaf(W[1],  a.w, r);
                r = fmaf(W[2],  b.x, r);
                r = fmaf(W[3],  b.y, r);
                r = fmaf(W[4],  b.z, r);
                r = fmaf(W[5],  b.w, r);
                r = fmaf(W[6],  c.x, r);
                r = fmaf(W[7],  c.y, r);
                r = fmaf(W[8],  c.z, r);
                r = fmaf(W[9],  c.w, r);
                r = fmaf(W[10], d.x, r);
                r = fmaf(W[11], d.y, r);
                r = fmaf(W[12], d.z, r);
                r = fmaf(W[13], d.w, r);
                r = fmaf(W[14], e.x, r);
                r = fmaf(W[15], e.y, r);         // tap 15 = s[4oc+9]
            } else {
                r = 0.f;
#pragma unroll
                for (int k = 0; k < NTAP; ++k)
                    r = fmaf(W[k], srow[min(max(4 * oc - 6 + k, 0), IN_W - 1)], r);
            }
            outp[(size_t)j * OUT_W] = r;
        }
        __syncthreads();    // smem reused by next strip's V dump
    }
}

extern "C" void kernel_launch(void* const* d_in, const int* in_sizes, int n_in,
                              void* d_out, int out_size)
{
    const float* in  = (const float*)d_in[0];
    float*       out = (float*)d_out;

    const int nimg = in_sizes[0] / (IN_H * IN_W);       // 24

    dim3 grid(XBLKS, nimg);                             // 32 x 24 = 768 blocks
    bicubic_fused<<<grid, 256>>>(in, out);
}

// round 8
// speedup vs baseline: 1.2021x; 1.2021x over previous
#include <cuda_runtime.h>
#include <cstdint>

#define IN_H   1024
#define IN_W   1024
#define OUT_H  256
#define OUT_W  256
#define NTAP   16

#define VCHUNK 8                 // output rows per strip
#define G      4                 // input rows per cp.async group
#define NG     11                // 44 input rows = 11 groups
#define D      3                 // in_buf ring depth (2 groups always in flight)
#define STRIPS_PER_BLOCK 2
#define XBLKS  (OUT_H / VCHUNK / STRIPS_PER_BLOCK)   // 16

__device__ __forceinline__ void cp_async16(uint32_t dst_smem, const float* src) {
    asm volatile("cp.async.cg.shared.global [%0], [%1], 16;\n"
                 :: "r"(dst_smem), "l"(src) : "memory");
}
__device__ __forceinline__ void cp_commit() {
    asm volatile("cp.async.commit_group;\n" ::: "memory");
}
template <int N>
__device__ __forceinline__ void cp_wait() {
    asm volatile("cp.async.wait_group %0;\n" :: "n"(N) : "memory");
}

// horizontal 16-tap for one vertical-result row held in smem
__device__ __forceinline__ void hfilter(const float* __restrict__ srow,
                                        int oc, float* __restrict__ dst)
{
    constexpr float W[NTAP] = {
        -0.001708984375f, -0.010986328125f, -0.018310546875f, -0.011962890625f,
         0.022705078125f,  0.097412109375f,  0.181884765625f,  0.240966796875f,
         0.240966796875f,  0.181884765625f,  0.097412109375f,  0.022705078125f,
        -0.011962890625f, -0.018310546875f, -0.010986328125f, -0.001708984375f };
    float r;
    if (oc >= 2 && oc <= 253) {
        const float4* __restrict__ sv = (const float4*)srow + oc;
        const float4 a = sv[-2], b = sv[-1], c = sv[0], d = sv[1], e = sv[2];
        r = W[0] * a.z;
        r = fmaf(W[1],  a.w, r);  r = fmaf(W[2],  b.x, r);
        r = fmaf(W[3],  b.y, r);  r = fmaf(W[4],  b.z, r);
        r = fmaf(W[5],  b.w, r);  r = fmaf(W[6],  c.x, r);
        r = fmaf(W[7],  c.y, r);  r = fmaf(W[8],  c.z, r);
        r = fmaf(W[9],  c.w, r);  r = fmaf(W[10], d.x, r);
        r = fmaf(W[11], d.y, r);  r = fmaf(W[12], d.z, r);
        r = fmaf(W[13], d.w, r);  r = fmaf(W[14], e.x, r);
        r = fmaf(W[15], e.y, r);
    } else {
        r = 0.f;
#pragma unroll
        for (int k = 0; k < NTAP; ++k)
            r = fmaf(W[k], srow[min(max(4 * oc - 6 + k, 0), IN_W - 1)], r);
    }
    *dst = r;
}

__global__ __launch_bounds__(256)
void bicubic_fused(const float* __restrict__ in, float* __restrict__ out)
{
    constexpr float W[NTAP] = {
        -0.001708984375f, -0.010986328125f, -0.018310546875f, -0.011962890625f,
         0.022705078125f,  0.097412109375f,  0.181884765625f,  0.240966796875f,
         0.240966796875f,  0.181884765625f,  0.097412109375f,  0.022705078125f,
        -0.011962890625f, -0.018310546875f, -0.010986328125f, -0.001708984375f };

    __shared__ __align__(16) float in_buf[D][G][IN_W];   // 48 KB cp.async ring
    __shared__ __align__(16) float s_row[2][IN_W];       //  8 KB rotating V-result rows

    const int tid = threadIdx.x;                 // owns float4 column tid
    const int img = blockIdx.y;
    const float* __restrict__ inp = in + (size_t)img * (IN_H * IN_W);

#pragma unroll 1
    for (int it = 0; it < STRIPS_PER_BLOCK; ++it) {
        const int strip = blockIdx.x + XBLKS * it;       // adjacent strips co-run
        const int o0    = strip * VCHUNK;
        const int R0    = 4 * o0 - 6;
        float* __restrict__ outp = out + ((size_t)img * OUT_H + o0) * OUT_W;

        // prefetch: group g -> in_buf[g%D], 4 rows, 16 B per thread per row
        auto prefetch = [&](int g) {
#pragma unroll
            for (int r = 0; r < G; ++r) {
                const int gr = min(max(R0 + 4 * g + r, 0), IN_H - 1);
                const uint32_t dst = (uint32_t)__cvta_generic_to_shared(
                    &in_buf[g % D][r][4 * tid]);
                cp_async16(dst, inp + (size_t)gr * IN_W + 4 * tid);
            }
            cp_commit();
        };

        prefetch(0);
        prefetch(1);

        float4 acc[VCHUNK];
#pragma unroll
        for (int j = 0; j < VCHUNK; ++j) acc[j] = make_float4(0.f, 0.f, 0.f, 0.f);

#pragma unroll
        for (int g = 0; g < NG; ++g) {
            if (g < NG - 1) cp_wait<1>(); else cp_wait<0>();
            __syncthreads();                   // orders s_row STS(g-1) -> LDS(g)

            if (g + 2 < NG) prefetch(g + 2);   // keeps 2 groups in flight

            // H phase for output row (g-4), STS'd last iteration
            if (g >= 4)
                hfilter(s_row[g % 2], tid, outp + (size_t)(g - 4) * OUT_W + tid);

            // V phase: consume group g (own column only; no cross-thread deps)
#pragma unroll
            for (int r = 0; r < G; ++r) {
                const int i = 4 * g + r;
                const float4 v = ((const float4*)in_buf[g % D][r])[tid];
#pragma unroll
                for (int j = 0; j < VCHUNK; ++j) {
                    const int k = i - 4 * j;           // compile-time pruned
                    if (k >= 0 && k < NTAP) {
                        acc[j].x = fmaf(W[k], v.x, acc[j].x);
                        acc[j].y = fmaf(W[k], v.y, acc[j].y);
                        acc[j].z = fmaf(W[k], v.z, acc[j].z);
                        acc[j].w = fmaf(W[k], v.w, acc[j].w);
                    }
                }
            }

            // output row g-3 is now complete -> stage for next iteration's H
            if (g >= 3)
                ((float4*)s_row[(g - 3) % 2])[tid] = acc[g - 3];
        }

        __syncthreads();
        hfilter(s_row[1], tid, outp + (size_t)7 * OUT_W + tid);   // last row (j=7)
        __syncthreads();                       // s_row safe before next strip
    }
}

extern "C" void kernel_launch(void* const* d_in, const int* in_sizes, int n_in,
                              void* d_out, int out_size)
{
    const float* in  = (const float*)d_in[0];
    float*       out = (float*)d_out;

    const int nimg = in_sizes[0] / (IN_H * IN_W);       // 24

    dim3 grid(XBLKS, nimg);                             // 16 x 24 = 384 blocks
    bicubic_fused<<<grid, 256>>>(in, out);
}